// round 1
// baseline (speedup 1.0000x reference)
#include <cuda_runtime.h>

#define N_NODES 8192
#define DIN 512
#define DOUT 256

// ---------------- scratch (device globals; no allocs allowed) ----------------
__device__ float g_h[N_NODES * DOUT];
__device__ float g_xi[N_NODES];
__device__ float g_t[N_NODES];   // -mu_i  (branch threshold)
__device__ float g_R[N_NODES];   // exp(-0.8*mu_i)
__device__ float g_E1[N_NODES];  // exp(xi_j)
__device__ float g_Ea[N_NODES];  // exp(0.2*xi_j)

// ---------------- packed f32x2 FMA (full-rate on sm_103a) ----------------
__device__ __forceinline__ void ffma2(float2& d, float2 a, float2 b) {
    asm("fma.rn.f32x2 %0, %1, %2, %0;"
        : "+l"(*reinterpret_cast<unsigned long long*>(&d))
        : "l"(*reinterpret_cast<unsigned long long*>(&a)),
          "l"(*reinterpret_cast<unsigned long long*>(&b)));
}

// ---------------- K1: h = X @ W_phi  (8192x512 @ 512x256) ----------------
__global__ __launch_bounds__(256) void k1_gemm(const float* __restrict__ X,
                                               const float* __restrict__ W) {
    __shared__ float sX[16][64];
    __shared__ float sW[16][64];
    int t = threadIdx.x;
    int tx = t & 15, ty = t >> 4;
    int row0 = blockIdx.y * 64;
    int col0 = blockIdx.x * 64;
    float acc[4][4] = {};
    for (int k0 = 0; k0 < DIN; k0 += 16) {
        {   // X tile 64x16, transposed into sX[k][i]
            int i = t >> 2, k4 = (t & 3) * 4;
            float4 v = *(const float4*)(X + (size_t)(row0 + i) * DIN + k0 + k4);
            sX[k4 + 0][i] = v.x; sX[k4 + 1][i] = v.y;
            sX[k4 + 2][i] = v.z; sX[k4 + 3][i] = v.w;
        }
        {   // W tile 16x64
            int k = t >> 4, c4 = (t & 15) * 4;
            *(float4*)&sW[k][c4] =
                *(const float4*)(W + (size_t)(k0 + k) * DOUT + col0 + c4);
        }
        __syncthreads();
#pragma unroll
        for (int kk = 0; kk < 16; ++kk) {
            float a[4], b[4];
            *(float4*)a = *(float4*)&sX[kk][ty * 4];
            *(float4*)b = *(float4*)&sW[kk][tx * 4];
#pragma unroll
            for (int i = 0; i < 4; ++i)
#pragma unroll
                for (int j = 0; j < 4; ++j) acc[i][j] += a[i] * b[j];
        }
        __syncthreads();
    }
#pragma unroll
    for (int i = 0; i < 4; ++i) {
        float4 v = make_float4(acc[i][0], acc[i][1], acc[i][2], acc[i][3]);
        *(float4*)(g_h + (size_t)(row0 + ty * 4 + i) * DOUT + col0 + tx * 4) = v;
    }
}

// ---------------- K2: mu/xi + per-node exponential factors ----------------
__global__ __launch_bounds__(256) void k2_rowvec(const float* __restrict__ wmu,
                                                 const float* __restrict__ wxi) {
    int warp = threadIdx.x >> 5, lane = threadIdx.x & 31;
    int row = blockIdx.x * 8 + warp;
    const float* hrow = g_h + (size_t)row * DOUT;
    float smu = 0.f, sxi = 0.f;
#pragma unroll
    for (int q = 0; q < 8; ++q) {
        int c = lane + q * 32;
        float hv = hrow[c];
        smu += hv * wmu[c];
        sxi += hv * wxi[c];
    }
#pragma unroll
    for (int o = 16; o > 0; o >>= 1) {
        smu += __shfl_xor_sync(0xffffffff, smu, o);
        sxi += __shfl_xor_sync(0xffffffff, sxi, o);
    }
    if (lane == 0) {
        g_xi[row] = sxi;
        g_t[row]  = -smu;
        g_R[row]  = expf(-0.8f * smu);
        g_E1[row] = expf(sxi);
        g_Ea[row] = expf(0.2f * sxi);
    }
}

// ---------------- K3: fused masked-softmax GEMM + ELU ----------------
// CTA tile: 64 rows x 128 cols, K-loop over all 8192 nodes in chunks of 64.
// Weight tile computed on the fly from adjacency (no exp in the N^2 loop).
#define BR 64
#define BK 64
#define BC 128

__global__ __launch_bounds__(256, 2) void k3_attn(const int* __restrict__ adj,
                                                  float* __restrict__ out) {
    extern __shared__ float smem[];
    float* sA   = smem;                    // [BK][BR] weights (j-major)
    float* sB   = sA + BK * BR;            // [BK][BC] h tile
    float* sT   = sB + BK * BC;            // [BR] thresholds
    float* sR   = sT + BR;                 // [BR] exp(-0.8 mu)
    float* sDen = sR + BR;                 // [BR] denominators

    int t = threadIdx.x;
    int row0 = blockIdx.x * BR;
    int col0 = blockIdx.y * BC;
    if (t < BR) { sT[t] = g_t[row0 + t]; sR[t] = g_R[row0 + t]; }

    int tx = t & 31;        // col group: cols tx*4 .. tx*4+3
    int ty = t >> 5;        // row group: rows ty*8 .. ty*8+7
    int jj = (t & 15) * 4;  // this thread's j offset within chunk (w compute)
    int ib = t >> 4;        // base i for w compute (0..15)

    float2 acc2[4][4];      // [row-pair][col] : rows ty*8+2p, ty*8+2p+1
#pragma unroll
    for (int p = 0; p < 4; ++p)
#pragma unroll
        for (int c = 0; c < 4; ++c) acc2[p][c] = make_float2(0.f, 0.f);
    float den = 0.f;

    __syncthreads();

    for (int k0 = 0; k0 < N_NODES; k0 += BK) {
        // per-chunk j-local factors (same 4 j's for this thread each chunk)
        float4 xi4 = *(const float4*)(g_xi + k0 + jj);
        float4 e14 = *(const float4*)(g_E1 + k0 + jj);
        float4 ea4 = *(const float4*)(g_Ea + k0 + jj);
        __syncthreads();  // previous chunk's reads done before overwrite

        // ---- compute weight tile w[j][i] from adjacency ----
#pragma unroll
        for (int q = 0; q < 4; ++q) {
            int i = ib + q * 16;
            float ti = sT[i], Ri = sR[i];
            int4 a = *(const int4*)(adj + (size_t)(row0 + i) * N_NODES + k0 + jj);
            sA[(jj + 0) * BR + i] = a.x ? (xi4.x >= ti ? e14.x : Ri * ea4.x) : 0.f;
            sA[(jj + 1) * BR + i] = a.y ? (xi4.y >= ti ? e14.y : Ri * ea4.y) : 0.f;
            sA[(jj + 2) * BR + i] = a.z ? (xi4.z >= ti ? e14.z : Ri * ea4.z) : 0.f;
            sA[(jj + 3) * BR + i] = a.w ? (xi4.w >= ti ? e14.w : Ri * ea4.w) : 0.f;
        }
        // ---- load h tile [BK][BC] ----
#pragma unroll
        for (int q = 0; q < 8; ++q) {
            int idx = t + 256 * q;          // float4 index; BC/4=32 per row
            int j = idx >> 5;
            int c4 = (idx & 31) * 4;
            *(float4*)&sB[j * BC + c4] =
                *(const float4*)(g_h + (size_t)(k0 + j) * DOUT + col0 + c4);
        }
        __syncthreads();

        // ---- denominator partials (threads 0..63, one per row) ----
        if (t < BR) {
            float s = 0.f;
#pragma unroll
            for (int kk = 0; kk < BK; ++kk) s += sA[kk * BR + t];
            den += s;
        }

        // ---- register-blocked MAC, packed f32x2 ----
#pragma unroll 8
        for (int kk = 0; kk < BK; ++kk) {
            float4 alo = *(float4*)&sA[kk * BR + ty * 8];      // rows 0..3 (pairs free)
            float4 ahi = *(float4*)&sA[kk * BR + ty * 8 + 4];  // rows 4..7
            float4 b4  = *(float4*)&sB[kk * BC + tx * 4];
            float2 ap[4];
            ap[0] = make_float2(alo.x, alo.y);
            ap[1] = make_float2(alo.z, alo.w);
            ap[2] = make_float2(ahi.x, ahi.y);
            ap[3] = make_float2(ahi.z, ahi.w);
            float2 bp[4];
            bp[0] = make_float2(b4.x, b4.x);
            bp[1] = make_float2(b4.y, b4.y);
            bp[2] = make_float2(b4.z, b4.z);
            bp[3] = make_float2(b4.w, b4.w);
#pragma unroll
            for (int p = 0; p < 4; ++p)
#pragma unroll
                for (int c = 0; c < 4; ++c) ffma2(acc2[p][c], ap[p], bp[c]);
        }
    }

    if (t < BR) sDen[t] = den;
    __syncthreads();

    // ---- epilogue: normalize + ELU, write out ----
#pragma unroll
    for (int p = 0; p < 4; ++p) {
#pragma unroll
        for (int half = 0; half < 2; ++half) {
            int r = ty * 8 + 2 * p + half;
            float inv = 1.f / sDen[r];
            float4 v;
            v.x = acc2[p][0].x * inv; v.y = acc2[p][1].x * inv;
            v.z = acc2[p][2].x * inv; v.w = acc2[p][3].x * inv;
            if (half) {
                v.x = acc2[p][0].y * inv; v.y = acc2[p][1].y * inv;
                v.z = acc2[p][2].y * inv; v.w = acc2[p][3].y * inv;
            }
            v.x = v.x > 0.f ? v.x : expm1f(v.x);
            v.y = v.y > 0.f ? v.y : expm1f(v.y);
            v.z = v.z > 0.f ? v.z : expm1f(v.z);
            v.w = v.w > 0.f ? v.w : expm1f(v.w);
            *(float4*)(out + (size_t)(row0 + r) * DOUT + col0 + tx * 4) = v;
        }
    }
}

// ---------------- launch ----------------
extern "C" void kernel_launch(void* const* d_in, const int* in_sizes, int n_in,
                              void* d_out, int out_size) {
    const float* features = (const float*)d_in[0];
    const int*   adj      = (const int*)d_in[1];
    const float* W_phi    = (const float*)d_in[2];
    const float* w_mu     = (const float*)d_in[3];
    const float* w_xi     = (const float*)d_in[4];
    float* out = (float*)d_out;

    k1_gemm<<<dim3(DOUT / 64, N_NODES / 64), 256>>>(features, W_phi);
    k2_rowvec<<<N_NODES / 8, 256>>>(w_mu, w_xi);

    int smem_bytes = (BK * BR + BK * BC + 3 * BR) * (int)sizeof(float);
    static int attr_set = 0;
    if (!attr_set) {
        cudaFuncSetAttribute(k3_attn, cudaFuncAttributeMaxDynamicSharedMemorySize,
                             smem_bytes);
        attr_set = 1;
    }
    k3_attn<<<dim3(N_NODES / BR, DOUT / BC), 256, smem_bytes>>>(adj, out);
}

// round 4
// speedup vs baseline: 1.4360x; 1.4360x over previous
#include <cuda_runtime.h>
#include <cuda_fp16.h>
#include <cstdint>

#define N_NODES 8192
#define DIN 512
#define DOUT 256

// ---------------- scratch (device globals; no allocs allowed) ----------------
__device__ float  g_h[N_NODES * DOUT];
__device__ __half g_hT[DOUT * N_NODES];   // fp16, transposed [chan][node]
__device__ float  g_xi[N_NODES];
__device__ float  g_t[N_NODES];   // -mu_i  (branch threshold)
__device__ float  g_R[N_NODES];   // exp(-0.8*mu_i)
__device__ float  g_E1[N_NODES];  // exp(xi_j)
__device__ float  g_Ea[N_NODES];  // exp(0.2*xi_j)

// ---------------- helpers ----------------
__device__ __forceinline__ void ffma2(float2& d, float2 a, float2 b) {
    asm("fma.rn.f32x2 %0, %1, %2, %0;"
        : "+l"(*reinterpret_cast<unsigned long long*>(&d))
        : "l"(*reinterpret_cast<unsigned long long*>(&a)),
          "l"(*reinterpret_cast<unsigned long long*>(&b)));
}
__device__ __forceinline__ uint32_t smem_u32(const void* p) {
    uint32_t a;
    asm("{ .reg .u64 t; cvta.to.shared.u64 t, %1; cvt.u32.u64 %0, t; }"
        : "=r"(a) : "l"(p));
    return a;
}
#define STS128(addr, a, b, c, d) \
    asm volatile("st.shared.v4.b32 [%0], {%1,%2,%3,%4};" \
                 :: "r"(addr), "r"(a), "r"(b), "r"(c), "r"(d) : "memory")
#define LDSM4(r0, r1, r2, r3, addr) \
    asm volatile("ldmatrix.sync.aligned.m8n8.x4.shared.b16 {%0,%1,%2,%3}, [%4];" \
                 : "=r"(r0), "=r"(r1), "=r"(r2), "=r"(r3) : "r"(addr))

__device__ __forceinline__ void mma16816(float* c, const uint32_t* a,
                                         const uint32_t* b) {
    asm volatile(
        "mma.sync.aligned.m16n8k16.row.col.f32.f16.f16.f32 "
        "{%0,%1,%2,%3}, {%4,%5,%6,%7}, {%8,%9}, {%0,%1,%2,%3};"
        : "+f"(c[0]), "+f"(c[1]), "+f"(c[2]), "+f"(c[3])
        : "r"(a[0]), "r"(a[1]), "r"(a[2]), "r"(a[3]), "r"(b[0]), "r"(b[1]));
}

// ---------------- K1: h = X @ W_phi  (f32x2 packed FMA) ----------------
__global__ __launch_bounds__(256) void k1_gemm(const float* __restrict__ X,
                                               const float* __restrict__ W) {
    __shared__ float sX[16][64];
    __shared__ float sW[16][64];
    int t = threadIdx.x;
    int tx = t & 15, ty = t >> 4;
    int row0 = blockIdx.y * 64;
    int col0 = blockIdx.x * 64;
    float2 acc2[2][4];
#pragma unroll
    for (int p = 0; p < 2; ++p)
#pragma unroll
        for (int j = 0; j < 4; ++j) acc2[p][j] = make_float2(0.f, 0.f);
    for (int k0 = 0; k0 < DIN; k0 += 16) {
        {
            int i = t >> 2, k4 = (t & 3) * 4;
            float4 v = *(const float4*)(X + (size_t)(row0 + i) * DIN + k0 + k4);
            sX[k4 + 0][i] = v.x; sX[k4 + 1][i] = v.y;
            sX[k4 + 2][i] = v.z; sX[k4 + 3][i] = v.w;
        }
        {
            int k = t >> 4, c4 = (t & 15) * 4;
            *(float4*)&sW[k][c4] =
                *(const float4*)(W + (size_t)(k0 + k) * DOUT + col0 + c4);
        }
        __syncthreads();
#pragma unroll
        for (int kk = 0; kk < 16; ++kk) {
            float4 a4 = *(float4*)&sX[kk][ty * 4];
            float4 b4 = *(float4*)&sW[kk][tx * 4];
            float2 ap[2] = {make_float2(a4.x, a4.y), make_float2(a4.z, a4.w)};
            float2 bp[4] = {make_float2(b4.x, b4.x), make_float2(b4.y, b4.y),
                            make_float2(b4.z, b4.z), make_float2(b4.w, b4.w)};
#pragma unroll
            for (int p = 0; p < 2; ++p)
#pragma unroll
                for (int j = 0; j < 4; ++j) ffma2(acc2[p][j], ap[p], bp[j]);
        }
        __syncthreads();
    }
#pragma unroll
    for (int p = 0; p < 2; ++p) {
        float4 v0 = make_float4(acc2[p][0].x, acc2[p][1].x, acc2[p][2].x, acc2[p][3].x);
        float4 v1 = make_float4(acc2[p][0].y, acc2[p][1].y, acc2[p][2].y, acc2[p][3].y);
        *(float4*)(g_h + (size_t)(row0 + ty * 4 + 2 * p + 0) * DOUT + col0 + tx * 4) = v0;
        *(float4*)(g_h + (size_t)(row0 + ty * 4 + 2 * p + 1) * DOUT + col0 + tx * 4) = v1;
    }
}

// ---------------- K2: mu/xi + per-node exponential factors ----------------
__global__ __launch_bounds__(256) void k2_rowvec(const float* __restrict__ wmu,
                                                 const float* __restrict__ wxi) {
    int warp = threadIdx.x >> 5, lane = threadIdx.x & 31;
    int row = blockIdx.x * 8 + warp;
    const float* hrow = g_h + (size_t)row * DOUT;
    float smu = 0.f, sxi = 0.f;
#pragma unroll
    for (int q = 0; q < 8; ++q) {
        int c = lane + q * 32;
        float hv = hrow[c];
        smu += hv * wmu[c];
        sxi += hv * wxi[c];
    }
#pragma unroll
    for (int o = 16; o > 0; o >>= 1) {
        smu += __shfl_xor_sync(0xffffffff, smu, o);
        sxi += __shfl_xor_sync(0xffffffff, sxi, o);
    }
    if (lane == 0) {
        g_xi[row] = sxi;
        g_t[row]  = -smu;
        g_R[row]  = expf(-0.8f * smu);
        g_E1[row] = expf(sxi);
        g_Ea[row] = expf(0.2f * sxi);
    }
}

// ---------------- K2t: hT[c][n] = (half)h[n][c] ----------------
__global__ __launch_bounds__(256) void k2t_transpose() {
    __shared__ float sm[64][33];
    int t = threadIdx.x;
    int tx = t & 31, ty = t >> 5;            // 32 x 8
    int r0 = blockIdx.x * 64;                // node tile
    int c0 = blockIdx.y * 32;                // chan tile
#pragma unroll
    for (int q = 0; q < 8; ++q)
        sm[ty + 8 * q][tx] = g_h[(size_t)(r0 + ty + 8 * q) * DOUT + c0 + tx];
    __syncthreads();
#pragma unroll
    for (int q = 0; q < 4; ++q) {
        int c = ty + 8 * q;
        __half2 v = __floats2half2_rn(sm[2 * tx][c], sm[2 * tx + 1][c]);
        *(__half2*)(g_hT + (size_t)(c0 + c) * N_NODES + r0 + 2 * tx) = v;
    }
}

// ---------------- K3: fused masked-softmax GEMM via mma.sync ----------------
// 128 CTAs: M=64 rows x N=256 channels. K over 8192 in chunks of 64.
// sA [64][72] halfs (w tile), sB [256][72] halfs (hT tile), double-buffered.
#define BR3 64
#define BK3 64
#define APITCH 72
#define SA_BYTES (BR3 * APITCH * 2)     // 9216
#define SB_BYTES (256 * APITCH * 2)     // 36864
#define K3_SMEM (2 * (SA_BYTES + SB_BYTES))

__global__ __launch_bounds__(256, 1) void k3_attn(const int* __restrict__ adj,
                                                  float* __restrict__ out) {
    extern __shared__ char dsm[];
    __shared__ float sPart[256];
    __shared__ float sDen[BR3];

    uint32_t base = smem_u32(dsm);
    uint32_t sAb[2] = {base, base + SA_BYTES};
    uint32_t sBb[2] = {base + 2 * SA_BYTES, base + 2 * SA_BYTES + SB_BYTES};

    int t = threadIdx.x;
    int w = t >> 5, lane = t & 31;
    int row0 = blockIdx.x * BR3;

    // weight-gen mapping: row gi, k-stripe of 16
    int gi = t >> 2;
    int gk = (t & 3) * 16;
    float ti = g_t[row0 + gi];
    float Ri = g_R[row0 + gi];
    float den = 0.f;

    // mma mapping
    int m_base = (w >> 2) * 32;      // 2 row-halves
    int n_base = (w & 3) * 64;       // 4 col-quarters
    float acc[2][8][4];
#pragma unroll
    for (int mt = 0; mt < 2; ++mt)
#pragma unroll
        for (int nt = 0; nt < 8; ++nt)
#pragma unroll
            for (int q = 0; q < 4; ++q) acc[mt][nt][q] = 0.f;

    const int4* aptr = (const int4*)(adj + (size_t)(row0 + gi) * N_NODES + gk);
    int4 areg[4];
#pragma unroll
    for (int q = 0; q < 4; ++q) areg[q] = aptr[q];

    // ldsm lane addressing (constant across chunks)
    int a_lrow = (lane < 16) ? lane : lane - 16;
    int a_chi  = (lane & 16) ? 8 : 0;
    int b_lrow = (lane & 7) + ((lane & 16) ? 8 : 0);
    int b_chi  = (lane & 8) ? 8 : 0;

    for (int c = 0; c < N_NODES / BK3; ++c) {
        int s = c & 1;
        int k0 = c * BK3;

        // ---- B tile: thread t loads n-row t, 128 bytes ----
        const uint4* bsrc = (const uint4*)(g_hT + (size_t)t * N_NODES + k0);
        uint4 bv[8];
#pragma unroll
        for (int q = 0; q < 8; ++q) bv[q] = bsrc[q];

        // ---- weight gen: 16 elems from prefetched adjacency ----
        uint32_t u[8];
#pragma unroll
        for (int q = 0; q < 4; ++q) {
            int jo = k0 + gk + q * 4;
            int4 a = areg[q];
            float4 x = *(const float4*)(g_xi + jo);
            float4 e = *(const float4*)(g_E1 + jo);
            float4 f = *(const float4*)(g_Ea + jo);
            float w0 = a.x ? (x.x >= ti ? e.x : Ri * f.x) : 0.f;
            float w1 = a.y ? (x.y >= ti ? e.y : Ri * f.y) : 0.f;
            float w2 = a.z ? (x.z >= ti ? e.z : Ri * f.z) : 0.f;
            float w3 = a.w ? (x.w >= ti ? e.w : Ri * f.w) : 0.f;
            den += (w0 + w1) + (w2 + w3);
            __half2 p0 = __floats2half2_rn(w0, w1);
            __half2 p1 = __floats2half2_rn(w2, w3);
            u[q * 2 + 0] = *(uint32_t*)&p0;
            u[q * 2 + 1] = *(uint32_t*)&p1;
        }
        uint32_t adst = sAb[s] + (uint32_t)(gi * APITCH + gk) * 2;
        STS128(adst,      u[0], u[1], u[2], u[3]);
        STS128(adst + 16, u[4], u[5], u[6], u[7]);

        uint32_t bdst = sBb[s] + (uint32_t)(t * APITCH) * 2;
#pragma unroll
        for (int q = 0; q < 8; ++q)
            STS128(bdst + q * 16, bv[q].x, bv[q].y, bv[q].z, bv[q].w);

        __syncthreads();

        // prefetch next chunk's adjacency during mma
        if (c + 1 < N_NODES / BK3) {
#pragma unroll
            for (int q = 0; q < 4; ++q) areg[q] = aptr[(c + 1) * 16 + q];
        }

        // ---- mma over the chunk: 4 k-steps ----
#pragma unroll
        for (int ks = 0; ks < 4; ++ks) {
            uint32_t af[2][4];
            uint32_t a0 = sAb[s] +
                (uint32_t)((m_base + a_lrow) * APITCH + ks * 16 + a_chi) * 2;
            LDSM4(af[0][0], af[0][1], af[0][2], af[0][3], a0);
            LDSM4(af[1][0], af[1][1], af[1][2], af[1][3], a0 + 16 * APITCH * 2);

            uint32_t bf[8][2];
#pragma unroll
            for (int p = 0; p < 4; ++p) {
                uint32_t ba = sBb[s] +
                    (uint32_t)((n_base + p * 16 + b_lrow) * APITCH + ks * 16 + b_chi) * 2;
                LDSM4(bf[2 * p][0], bf[2 * p][1], bf[2 * p + 1][0], bf[2 * p + 1][1], ba);
            }
#pragma unroll
            for (int mt = 0; mt < 2; ++mt)
#pragma unroll
                for (int nt = 0; nt < 8; ++nt)
                    mma16816(acc[mt][nt], af[mt], bf[nt]);
        }
        __syncthreads();
    }

    // ---- denominator reduction ----
    sPart[t] = den;
    __syncthreads();
    if (t < BR3)
        sDen[t] = sPart[4 * t] + sPart[4 * t + 1] + sPart[4 * t + 2] + sPart[4 * t + 3];
    __syncthreads();

    // ---- epilogue: normalize + ELU ----
    int g = lane >> 2, tq = lane & 3;
#pragma unroll
    for (int mt = 0; mt < 2; ++mt) {
        int ra = m_base + mt * 16 + g;
        int rb = ra + 8;
        float inva = 1.f / sDen[ra];
        float invb = 1.f / sDen[rb];
#pragma unroll
        for (int nt = 0; nt < 8; ++nt) {
            int col = n_base + nt * 8 + 2 * tq;
            float v0 = acc[mt][nt][0] * inva;
            float v1 = acc[mt][nt][1] * inva;
            float v2 = acc[mt][nt][2] * invb;
            float v3 = acc[mt][nt][3] * invb;
            v0 = v0 > 0.f ? v0 : expm1f(v0);
            v1 = v1 > 0.f ? v1 : expm1f(v1);
            v2 = v2 > 0.f ? v2 : expm1f(v2);
            v3 = v3 > 0.f ? v3 : expm1f(v3);
            *(float2*)(out + (size_t)(row0 + ra) * DOUT + col) = make_float2(v0, v1);
            *(float2*)(out + (size_t)(row0 + rb) * DOUT + col) = make_float2(v2, v3);
        }
    }
}

// ---------------- launch ----------------
extern "C" void kernel_launch(void* const* d_in, const int* in_sizes, int n_in,
                              void* d_out, int out_size) {
    const float* features = (const float*)d_in[0];
    const int*   adj      = (const int*)d_in[1];
    const float* W_phi    = (const float*)d_in[2];
    const float* w_mu     = (const float*)d_in[3];
    const float* w_xi     = (const float*)d_in[4];
    float* out = (float*)d_out;

    static int attr_set = 0;
    if (!attr_set) {
        cudaFuncSetAttribute(k3_attn, cudaFuncAttributeMaxDynamicSharedMemorySize,
                             K3_SMEM);
        attr_set = 1;
    }

    k1_gemm<<<dim3(DOUT / 64, N_NODES / 64), 256>>>(features, W_phi);
    k2_rowvec<<<N_NODES / 8, 256>>>(w_mu, w_xi);
    k2t_transpose<<<dim3(N_NODES / 64, DOUT / 32), 256>>>();
    k3_attn<<<N_NODES / BR3, 256, K3_SMEM>>>(adj, out);
}

// round 6
// speedup vs baseline: 2.8026x; 1.9517x over previous
#include <cuda_runtime.h>
#include <cuda_fp16.h>
#include <cstdint>

#define N_NODES 8192
#define DIN 512
#define DOUT 256

// ---------------- scratch (device globals; no allocs allowed) ----------------
__device__ float  g_h[N_NODES * DOUT];
__device__ __half g_hT[DOUT * N_NODES];   // fp16, transposed [chan][node]
__device__ float  g_xi[N_NODES];
__device__ float  g_t[N_NODES];   // -mu_i  (branch threshold)
__device__ float  g_R[N_NODES];   // exp(-0.8*mu_i)
__device__ float  g_E1[N_NODES];  // exp(xi_j)
__device__ float  g_Ea[N_NODES];  // exp(0.2*xi_j)

// ---------------- helpers ----------------
__device__ __forceinline__ void ffma2(float2& d, float2 a, float2 b) {
    asm("fma.rn.f32x2 %0, %1, %2, %0;"
        : "+l"(*reinterpret_cast<unsigned long long*>(&d))
        : "l"(*reinterpret_cast<unsigned long long*>(&a)),
          "l"(*reinterpret_cast<unsigned long long*>(&b)));
}
__device__ __forceinline__ uint32_t smem_u32(const void* p) {
    uint32_t a;
    asm("{ .reg .u64 t; cvta.to.shared.u64 t, %1; cvt.u32.u64 %0, t; }"
        : "=r"(a) : "l"(p));
    return a;
}
#define STS128(addr, a, b, c, d) \
    asm volatile("st.shared.v4.b32 [%0], {%1,%2,%3,%4};" \
                 :: "r"(addr), "r"(a), "r"(b), "r"(c), "r"(d) : "memory")
#define LDSM4(r0, r1, r2, r3, addr) \
    asm volatile("ldmatrix.sync.aligned.m8n8.x4.shared.b16 {%0,%1,%2,%3}, [%4];" \
                 : "=r"(r0), "=r"(r1), "=r"(r2), "=r"(r3) : "r"(addr))
#define CP_ASYNC16(dst, src) \
    asm volatile("cp.async.cg.shared.global [%0], [%1], 16;" \
                 :: "r"(dst), "l"(src) : "memory")
#define CP_COMMIT() asm volatile("cp.async.commit_group;" ::: "memory")
#define CP_WAIT0()  asm volatile("cp.async.wait_group 0;" ::: "memory")

__device__ __forceinline__ void mma16816(float* c, const uint32_t* a,
                                         const uint32_t* b) {
    asm volatile(
        "mma.sync.aligned.m16n8k16.row.col.f32.f16.f16.f32 "
        "{%0,%1,%2,%3}, {%4,%5,%6,%7}, {%8,%9}, {%0,%1,%2,%3};"
        : "+f"(c[0]), "+f"(c[1]), "+f"(c[2]), "+f"(c[3])
        : "r"(a[0]), "r"(a[1]), "r"(a[2]), "r"(a[3]), "r"(b[0]), "r"(b[1]));
}

// ---------------- K1: h = X @ W_phi  (f32x2 packed FMA) ----------------
__global__ __launch_bounds__(256) void k1_gemm(const float* __restrict__ X,
                                               const float* __restrict__ W) {
    __shared__ float sX[16][64];
    __shared__ float sW[16][64];
    int t = threadIdx.x;
    int tx = t & 15, ty = t >> 4;
    int row0 = blockIdx.y * 64;
    int col0 = blockIdx.x * 64;
    float2 acc2[2][4];
#pragma unroll
    for (int p = 0; p < 2; ++p)
#pragma unroll
        for (int j = 0; j < 4; ++j) acc2[p][j] = make_float2(0.f, 0.f);
    for (int k0 = 0; k0 < DIN; k0 += 16) {
        {
            int i = t >> 2, k4 = (t & 3) * 4;
            float4 v = *(const float4*)(X + (size_t)(row0 + i) * DIN + k0 + k4);
            sX[k4 + 0][i] = v.x; sX[k4 + 1][i] = v.y;
            sX[k4 + 2][i] = v.z; sX[k4 + 3][i] = v.w;
        }
        {
            int k = t >> 4, c4 = (t & 15) * 4;
            *(float4*)&sW[k][c4] =
                *(const float4*)(W + (size_t)(k0 + k) * DOUT + col0 + c4);
        }
        __syncthreads();
#pragma unroll
        for (int kk = 0; kk < 16; ++kk) {
            float4 a4 = *(float4*)&sX[kk][ty * 4];
            float4 b4 = *(float4*)&sW[kk][tx * 4];
            float2 ap[2] = {make_float2(a4.x, a4.y), make_float2(a4.z, a4.w)};
            float2 bp[4] = {make_float2(b4.x, b4.x), make_float2(b4.y, b4.y),
                            make_float2(b4.z, b4.z), make_float2(b4.w, b4.w)};
#pragma unroll
            for (int p = 0; p < 2; ++p)
#pragma unroll
                for (int j = 0; j < 4; ++j) ffma2(acc2[p][j], ap[p], bp[j]);
        }
        __syncthreads();
    }
#pragma unroll
    for (int p = 0; p < 2; ++p) {
        float4 v0 = make_float4(acc2[p][0].x, acc2[p][1].x, acc2[p][2].x, acc2[p][3].x);
        float4 v1 = make_float4(acc2[p][0].y, acc2[p][1].y, acc2[p][2].y, acc2[p][3].y);
        *(float4*)(g_h + (size_t)(row0 + ty * 4 + 2 * p + 0) * DOUT + col0 + tx * 4) = v0;
        *(float4*)(g_h + (size_t)(row0 + ty * 4 + 2 * p + 1) * DOUT + col0 + tx * 4) = v1;
    }
}

// ---------------- K2: mu/xi + per-node exponential factors ----------------
__global__ __launch_bounds__(256) void k2_rowvec(const float* __restrict__ wmu,
                                                 const float* __restrict__ wxi) {
    int warp = threadIdx.x >> 5, lane = threadIdx.x & 31;
    int row = blockIdx.x * 8 + warp;
    const float* hrow = g_h + (size_t)row * DOUT;
    float smu = 0.f, sxi = 0.f;
#pragma unroll
    for (int q = 0; q < 8; ++q) {
        int c = lane + q * 32;
        float hv = hrow[c];
        smu += hv * wmu[c];
        sxi += hv * wxi[c];
    }
#pragma unroll
    for (int o = 16; o > 0; o >>= 1) {
        smu += __shfl_xor_sync(0xffffffff, smu, o);
        sxi += __shfl_xor_sync(0xffffffff, sxi, o);
    }
    if (lane == 0) {
        g_xi[row] = sxi;
        g_t[row]  = -smu;
        g_R[row]  = expf(-0.8f * smu);
        g_E1[row] = expf(sxi);
        g_Ea[row] = expf(0.2f * sxi);
    }
}

// ---------------- K2t: hT[c][n] = (half)h[n][c] ----------------
__global__ __launch_bounds__(256) void k2t_transpose() {
    __shared__ float sm[64][33];
    int t = threadIdx.x;
    int tx = t & 31, ty = t >> 5;            // 32 x 8
    int r0 = blockIdx.x * 64;                // node tile
    int c0 = blockIdx.y * 32;                // chan tile
#pragma unroll
    for (int q = 0; q < 8; ++q)
        sm[ty + 8 * q][tx] = g_h[(size_t)(r0 + ty + 8 * q) * DOUT + c0 + tx];
    __syncthreads();
#pragma unroll
    for (int q = 0; q < 4; ++q) {
        int c = ty + 8 * q;
        __half2 v = __floats2half2_rn(sm[2 * tx][c], sm[2 * tx + 1][c]);
        *(__half2*)(g_hT + (size_t)(c0 + c) * N_NODES + r0 + 2 * tx) = v;
    }
}

// ---------------- K3: fused masked-softmax GEMM via mma.sync ----------------
// 128 CTAs: M=64 rows x N=256 channels. K over 8192 in chunks of 128.
// cp.async double-buffered B tile; one __syncthreads per chunk.
#define BR3 64
#define BK3 128
#define PITCH 136
#define SA_BYTES (BR3 * PITCH * 2)      // 17408
#define SB_BYTES (256 * PITCH * 2)      // 69632
#define K3_SMEM (2 * (SA_BYTES + SB_BYTES))  // 174080

__global__ __launch_bounds__(256, 1) void k3_attn(const int* __restrict__ adj,
                                                  float* __restrict__ out) {
    extern __shared__ char dsm[];
    __shared__ float sPart[256];
    __shared__ float sDen[BR3];

    uint32_t base = smem_u32(dsm);
    uint32_t sAb[2] = {base, base + SA_BYTES};
    uint32_t sBb[2] = {base + 2 * SA_BYTES, base + 2 * SA_BYTES + SB_BYTES};

    int t = threadIdx.x;
    int w = t >> 5, lane = t & 31;
    int row0 = blockIdx.x * BR3;

    // weight-gen mapping: row gi, k-stripe of 32 within the 128-chunk
    int gi = t >> 2;
    int gk = (t & 3) * 32;
    float ti = g_t[row0 + gi];
    float Ri = g_R[row0 + gi];
    float den = 0.f;

    // mma mapping
    int m_base = (w >> 2) * 32;
    int n_base = (w & 3) * 64;
    float acc[2][8][4];
#pragma unroll
    for (int mt = 0; mt < 2; ++mt)
#pragma unroll
        for (int nt = 0; nt < 8; ++nt)
#pragma unroll
            for (int q = 0; q < 4; ++q) acc[mt][nt][q] = 0.f;

    const int4* aptr = (const int4*)(adj + (size_t)(row0 + gi) * N_NODES);
    int4 areg[8];
#pragma unroll
    for (int q = 0; q < 8; ++q) areg[q] = aptr[(gk >> 2) + q];   // chunk 0

    // B cp.async lane mapping: 16 lanes per 256B row-span, 16 rows per q-step
    int bn = t >> 4;
    int boff = (t & 15) * 16;
    // prologue: chunk 0 B tile -> stage 0
#pragma unroll
    for (int q = 0; q < 16; ++q) {
        int n = q * 16 + bn;
        const char* src = (const char*)(g_hT + (size_t)n * N_NODES) + boff;
        CP_ASYNC16(sBb[0] + (uint32_t)(n * (PITCH * 2)) + boff, src);
    }
    CP_COMMIT();

    // ldsm lane addressing (constant across chunks)
    int a_lrow = lane & 15;
    int a_chi  = (lane & 16) ? 8 : 0;
    int b_lrow = (lane & 7) + ((lane & 16) ? 8 : 0);
    int b_chi  = (lane & 8) ? 8 : 0;

    const int NCHUNK = N_NODES / BK3;   // 64
    for (int c = 0; c < NCHUNK; ++c) {
        int s = c & 1;
        int k0 = c * BK3;

        // ---- weight gen: 32 j's from prefetched adjacency ----
        uint32_t u[16];
#pragma unroll
        for (int q = 0; q < 8; ++q) {
            int jo = k0 + gk + q * 4;
            int4 a = areg[q];
            float4 x = *(const float4*)(g_xi + jo);
            float4 e = *(const float4*)(g_E1 + jo);
            float4 f = *(const float4*)(g_Ea + jo);
            float w0 = a.x ? (x.x >= ti ? e.x : Ri * f.x) : 0.f;
            float w1 = a.y ? (x.y >= ti ? e.y : Ri * f.y) : 0.f;
            float w2 = a.z ? (x.z >= ti ? e.z : Ri * f.z) : 0.f;
            float w3 = a.w ? (x.w >= ti ? e.w : Ri * f.w) : 0.f;
            den += (w0 + w1) + (w2 + w3);
            __half2 p0 = __floats2half2_rn(w0, w1);
            __half2 p1 = __floats2half2_rn(w2, w3);
            u[q * 2 + 0] = *(uint32_t*)&p0;
            u[q * 2 + 1] = *(uint32_t*)&p1;
        }
        uint32_t adst = sAb[s] + (uint32_t)(gi * PITCH + gk) * 2;
        STS128(adst,      u[0],  u[1],  u[2],  u[3]);
        STS128(adst + 16, u[4],  u[5],  u[6],  u[7]);
        STS128(adst + 32, u[8],  u[9],  u[10], u[11]);
        STS128(adst + 48, u[12], u[13], u[14], u[15]);

        // ---- prefetch next chunk's adjacency into regs ----
        if (c + 1 < NCHUNK) {
#pragma unroll
            for (int q = 0; q < 8; ++q)
                areg[q] = aptr[(((c + 1) * BK3 + gk) >> 2) + q];
        }

        CP_WAIT0();            // this chunk's B tile landed (own groups)
        __syncthreads();       // publish A + B tiles

        // ---- issue next chunk's B tile (in flight during mma) ----
        if (c + 1 < NCHUNK) {
            int nk0 = k0 + BK3;
#pragma unroll
            for (int q = 0; q < 16; ++q) {
                int n = q * 16 + bn;
                const char* src =
                    (const char*)(g_hT + (size_t)n * N_NODES + nk0) + boff;
                CP_ASYNC16(sBb[s ^ 1] + (uint32_t)(n * (PITCH * 2)) + boff, src);
            }
        }
        CP_COMMIT();

        // ---- mma over the chunk: 8 k-steps ----
#pragma unroll
        for (int ks = 0; ks < 8; ++ks) {
            uint32_t af[2][4];
            uint32_t a0 = sAb[s] +
                (uint32_t)((m_base + a_lrow) * PITCH + ks * 16 + a_chi) * 2;
            LDSM4(af[0][0], af[0][1], af[0][2], af[0][3], a0);
            LDSM4(af[1][0], af[1][1], af[1][2], af[1][3], a0 + 16 * PITCH * 2);

            uint32_t bf[8][2];
#pragma unroll
            for (int p = 0; p < 4; ++p) {
                uint32_t ba = sBb[s] +
                    (uint32_t)((n_base + p * 16 + b_lrow) * PITCH + ks * 16 + b_chi) * 2;
                LDSM4(bf[2 * p][0], bf[2 * p][1], bf[2 * p + 1][0], bf[2 * p + 1][1], ba);
            }
#pragma unroll
            for (int mt = 0; mt < 2; ++mt)
#pragma unroll
                for (int nt = 0; nt < 8; ++nt)
                    mma16816(acc[mt][nt], af[mt], bf[nt]);
        }
    }

    // ---- denominator reduction ----
    sPart[t] = den;
    __syncthreads();
    if (t < BR3)
        sDen[t] = sPart[4 * t] + sPart[4 * t + 1] + sPart[4 * t + 2] + sPart[4 * t + 3];
    __syncthreads();

    // ---- epilogue: normalize + ELU ----
    int g = lane >> 2, tq = lane & 3;
#pragma unroll
    for (int mt = 0; mt < 2; ++mt) {
        int ra = m_base + mt * 16 + g;
        int rb = ra + 8;
        float inva = 1.f / sDen[ra];
        float invb = 1.f / sDen[rb];
#pragma unroll
        for (int nt = 0; nt < 8; ++nt) {
            int col = n_base + nt * 8 + 2 * tq;
            float v0 = acc[mt][nt][0] * inva;
            float v1 = acc[mt][nt][1] * inva;
            float v2 = acc[mt][nt][2] * invb;
            float v3 = acc[mt][nt][3] * invb;
            v0 = v0 > 0.f ? v0 : expm1f(v0);
            v1 = v1 > 0.f ? v1 : expm1f(v1);
            v2 = v2 > 0.f ? v2 : expm1f(v2);
            v3 = v3 > 0.f ? v3 : expm1f(v3);
            *(float2*)(out + (size_t)(row0 + ra) * DOUT + col) = make_float2(v0, v1);
            *(float2*)(out + (size_t)(row0 + rb) * DOUT + col) = make_float2(v2, v3);
        }
    }
}

// ---------------- launch ----------------
extern "C" void kernel_launch(void* const* d_in, const int* in_sizes, int n_in,
                              void* d_out, int out_size) {
    const float* features = (const float*)d_in[0];
    const int*   adj      = (const int*)d_in[1];
    const float* W_phi    = (const float*)d_in[2];
    const float* w_mu     = (const float*)d_in[3];
    const float* w_xi     = (const float*)d_in[4];
    float* out = (float*)d_out;

    static int attr_set = 0;
    if (!attr_set) {
        cudaFuncSetAttribute(k3_attn, cudaFuncAttributeMaxDynamicSharedMemorySize,
                             K3_SMEM);
        attr_set = 1;
    }

    k1_gemm<<<dim3(DOUT / 64, N_NODES / 64), 256>>>(features, W_phi);
    k2_rowvec<<<N_NODES / 8, 256>>>(w_mu, w_xi);
    k2t_transpose<<<dim3(N_NODES / 64, DOUT / 32), 256>>>();
    k3_attn<<<N_NODES / BR3, 256, K3_SMEM>>>(adj, out);
}